// round 1
// baseline (speedup 1.0000x reference)
#include <cuda_runtime.h>
#include <cuda_bf16.h>
#include <math.h>

// ---------------- problem constants ----------------
#define Bn 8
#define Hn 192
#define Wn 192
#define Cn 64
#define NPIX (Bn*Hn*Wn)          // 294912
#define CV 81
#define CIN0 209
#define P0 212                    // padded stride for 209-channel tensors
#define FLOW_SCALE 271.52900393598527f   // sqrt(192^2 + 192^2)
#define BN_EPS 1e-3f

// ---------------- scratch (no cudaMalloc allowed) ----------------
__device__ float g_bufA[(size_t)NPIX * P0];   // ~250 MB
__device__ float g_bufB[(size_t)NPIX * P0];   // ~250 MB

// ---------------- helpers ----------------
__device__ __forceinline__ float mish(float x) {
    // softplus stable: max(x,0) + log1p(exp(-|x|))
    float sp = fmaxf(x, 0.f) + log1pf(expf(-fabsf(x)));
    return x * tanhf(sp);
}

// ---------------- kernel 1: cost volume + concat -> x0 [NPIX, 212] ----------------
__global__ void cost_concat_kernel(const float* __restrict__ prv,
                                   const float* __restrict__ nxt,
                                   float* __restrict__ x0)
{
    int pix = blockIdx.x * blockDim.x + threadIdx.x;
    if (pix >= NPIX) return;
    int w = pix % Wn;
    int h = (pix / Wn) % Hn;
    int b = pix / (Wn * Hn);

    const float4* p4 = (const float4*)(prv + (size_t)pix * Cn);
    float4 p[16];
#pragma unroll
    for (int t = 0; t < 16; t++) p[t] = p4[t];

    float* out = x0 + (size_t)pix * P0;

#pragma unroll 1
    for (int i = 0; i < 9; i++) {
        int hh = h + i - 4;
        bool hv = (hh >= 0) && (hh < Hn);
#pragma unroll 1
        for (int j = 0; j < 9; j++) {
            int ww = w + j - 4;
            float c = 0.f;
            if (hv && ww >= 0 && ww < Wn) {
                const float4* q4 = (const float4*)(nxt + ((size_t)((b * Hn + hh) * Wn + ww)) * Cn);
                float acc = 0.f;
#pragma unroll
                for (int t = 0; t < 16; t++) {
                    float4 q = q4[t];
                    acc += p[t].x * q.x + p[t].y * q.y + p[t].z * q.z + p[t].w * q.w;
                }
                c = acc * (1.f / 64.f);
                c = (c > 0.f) ? c : 0.1f * c;   // leaky_relu(0.1)
            }
            out[i * 9 + j] = c;
        }
    }
    // concat prv (from registers), nxt
#pragma unroll
    for (int t = 0; t < 16; t++) {
        out[CV + 4 * t + 0] = p[t].x;
        out[CV + 4 * t + 1] = p[t].y;
        out[CV + 4 * t + 2] = p[t].z;
        out[CV + 4 * t + 3] = p[t].w;
    }
    const float4* n4 = (const float4*)(nxt + (size_t)pix * Cn);
#pragma unroll
    for (int t = 0; t < 16; t++) {
        float4 q = n4[t];
        out[CV + Cn + 4 * t + 0] = q.x;
        out[CV + Cn + 4 * t + 1] = q.y;
        out[CV + Cn + 4 * t + 2] = q.z;
        out[CV + Cn + 4 * t + 3] = q.w;
    }
}

// ---------------- kernel 2: depthwise 3x3 SAME ----------------
// X,Y: [NPIX, stride] using first cin channels; Wd: [(3*3)*cin]
__global__ void dw_kernel(const float* __restrict__ X, const float* __restrict__ Wd,
                          float* __restrict__ Y, int cin, int stride)
{
    int idx = blockIdx.x * blockDim.x + threadIdx.x;
    int total = NPIX * cin;
    if (idx >= total) return;
    int c = idx % cin;
    int pix = idx / cin;
    int w = pix % Wn;
    int h = (pix / Wn) % Hn;
    int b = pix / (Wn * Hn);

    float acc = 0.f;
#pragma unroll
    for (int ky = 0; ky < 3; ky++) {
        int hh = h + ky - 1;
        if (hh < 0 || hh >= Hn) continue;
#pragma unroll
        for (int kx = 0; kx < 3; kx++) {
            int ww = w + kx - 1;
            if (ww < 0 || ww >= Wn) continue;
            float xv = X[((size_t)((b * Hn + hh) * Wn + ww)) * stride + c];
            acc += xv * Wd[(ky * 3 + kx) * cin + c];
        }
    }
    Y[(size_t)pix * stride + c] = acc;
}

// ---------------- kernel 3: pointwise GEMM + bias + mish ----------------
// X:[NPIX, strideK] (K valid channels), Wp:[K, BNv], bias:[BNv], Y:[NPIX, BNv]
// BM=64, BK=16, 256 threads, thread tile 4 x TN
template<int BNv, int TN>
__global__ void pw_mish_kernel(const float* __restrict__ X, const float* __restrict__ Wp,
                               const float* __restrict__ bias, float* __restrict__ Y,
                               int K, int strideK)
{
    __shared__ float As[16][64];
    __shared__ float Ws[16][BNv];

    int tid = threadIdx.x;
    int tx = tid % 16;        // n-group
    int ty = tid / 16;        // px-group (16 groups * 4 px)
    int block_px = blockIdx.x * 64;

    float acc[4][TN];
#pragma unroll
    for (int m = 0; m < 4; m++)
#pragma unroll
        for (int j = 0; j < TN; j++) acc[m][j] = 0.f;

    int a_px = tid >> 2;            // 0..63
    int a_k  = (tid & 3) * 4;       // 0,4,8,12
    const float* Arow = X + (size_t)(block_px + a_px) * strideK;

    for (int k0 = 0; k0 < K; k0 += 16) {
#pragma unroll
        for (int r = 0; r < 4; r++) {
            int k = k0 + a_k + r;
            As[a_k + r][a_px] = (k < K) ? Arow[k] : 0.f;
        }
#pragma unroll
        for (int i = tid; i < 16 * BNv; i += 256) {
            int kk = i / BNv, n = i % BNv;
            int k = k0 + kk;
            Ws[kk][n] = (k < K) ? Wp[k * BNv + n] : 0.f;
        }
        __syncthreads();
#pragma unroll
        for (int kk = 0; kk < 16; kk++) {
            float a0 = As[kk][ty * 4 + 0];
            float a1 = As[kk][ty * 4 + 1];
            float a2 = As[kk][ty * 4 + 2];
            float a3 = As[kk][ty * 4 + 3];
#pragma unroll
            for (int j = 0; j < TN; j++) {
                float bb = Ws[kk][tx * TN + j];
                acc[0][j] += a0 * bb;
                acc[1][j] += a1 * bb;
                acc[2][j] += a2 * bb;
                acc[3][j] += a3 * bb;
            }
        }
        __syncthreads();
    }

#pragma unroll
    for (int m = 0; m < 4; m++) {
        int px = block_px + ty * 4 + m;
        float* yrow = Y + (size_t)px * BNv;
#pragma unroll
        for (int j = 0; j < TN; j++) {
            int n = tx * TN + j;
            float v = acc[m][j] + bias[n];
            yrow[n] = mish(v);
        }
    }
}

// ---------------- kernel 4: BN + 3x3 flow conv + scale ----------------
// X:[NPIX,16], Wf:[3,3,16,2], out:[NPIX,2]
__global__ void final_kernel(const float* __restrict__ X,
                             const float* __restrict__ gamma, const float* __restrict__ beta,
                             const float* __restrict__ mean,  const float* __restrict__ var,
                             const float* __restrict__ Wf, float* __restrict__ out)
{
    int pix = blockIdx.x * blockDim.x + threadIdx.x;
    if (pix >= NPIX) return;
    int w = pix % Wn;
    int h = (pix / Wn) % Hn;
    int b = pix / (Wn * Hn);

    float sc[16], sh[16];
#pragma unroll
    for (int c = 0; c < 16; c++) {
        float s = gamma[c] * rsqrtf(var[c] + BN_EPS);
        sc[c] = s;
        sh[c] = beta[c] - mean[c] * s;
    }

    float f0 = 0.f, f1 = 0.f;
#pragma unroll
    for (int ky = 0; ky < 3; ky++) {
        int hh = h + ky - 1;
        if (hh < 0 || hh >= Hn) continue;
#pragma unroll
        for (int kx = 0; kx < 3; kx++) {
            int ww = w + kx - 1;
            if (ww < 0 || ww >= Wn) continue;
            const float* xr = X + ((size_t)((b * Hn + hh) * Wn + ww)) * 16;
            const float* wr = Wf + (ky * 3 + kx) * 16 * 2;
#pragma unroll
            for (int c = 0; c < 16; c++) {
                float xv = xr[c] * sc[c] + sh[c];
                f0 += xv * wr[c * 2 + 0];
                f1 += xv * wr[c * 2 + 1];
            }
        }
    }
    out[(size_t)pix * 2 + 0] = FLOW_SCALE * f0;
    out[(size_t)pix * 2 + 1] = FLOW_SCALE * f1;
}

// ---------------- launch ----------------
extern "C" void kernel_launch(void* const* d_in, const int* in_sizes, int n_in,
                              void* d_out, int out_size)
{
    const float* prv   = (const float*)d_in[0];
    const float* nxt   = (const float*)d_in[1];
    const float* dw0   = (const float*)d_in[2];
    const float* pw0   = (const float*)d_in[3];
    const float* b0    = (const float*)d_in[4];
    const float* dw1   = (const float*)d_in[5];
    const float* pw1   = (const float*)d_in[6];
    const float* b1    = (const float*)d_in[7];
    const float* dw2   = (const float*)d_in[8];
    const float* pw2   = (const float*)d_in[9];
    const float* b2    = (const float*)d_in[10];
    const float* dw3   = (const float*)d_in[11];
    const float* pw3   = (const float*)d_in[12];
    const float* b3    = (const float*)d_in[13];
    const float* bng   = (const float*)d_in[14];
    const float* bnb   = (const float*)d_in[15];
    const float* bnm   = (const float*)d_in[16];
    const float* bnv   = (const float*)d_in[17];
    const float* flw   = (const float*)d_in[18];
    float* out = (float*)d_out;

    float *A = nullptr, *Bb = nullptr;
    cudaGetSymbolAddress((void**)&A,  g_bufA);
    cudaGetSymbolAddress((void**)&Bb, g_bufB);

    // 1) cost volume + concat -> A [NPIX, 212] (209 valid)
    cost_concat_kernel<<<(NPIX + 127) / 128, 128>>>(prv, nxt, A);

    // layer 0: dw(A)->B, pw(B)->A(128)
    {
        int total = NPIX * CIN0;
        dw_kernel<<<(total + 255) / 256, 256>>>(A, dw0, Bb, CIN0, P0);
        pw_mish_kernel<128, 8><<<NPIX / 64, 256>>>(Bb, pw0, b0, A, CIN0, P0);
    }
    // layer 1: dw(A,128)->B, pw(B)->A(64)
    {
        int total = NPIX * 128;
        dw_kernel<<<(total + 255) / 256, 256>>>(A, dw1, Bb, 128, 128);
        pw_mish_kernel<64, 4><<<NPIX / 64, 256>>>(Bb, pw1, b1, A, 128, 128);
    }
    // layer 2: dw(A,64)->B, pw(B)->A(32)
    {
        int total = NPIX * 64;
        dw_kernel<<<(total + 255) / 256, 256>>>(A, dw2, Bb, 64, 64);
        pw_mish_kernel<32, 2><<<NPIX / 64, 256>>>(Bb, pw2, b2, A, 64, 64);
    }
    // layer 3: dw(A,32)->B, pw(B)->A(16)
    {
        int total = NPIX * 32;
        dw_kernel<<<(total + 255) / 256, 256>>>(A, dw3, Bb, 32, 32);
        pw_mish_kernel<16, 1><<<NPIX / 64, 256>>>(Bb, pw3, b3, A, 32, 32);
    }
    // BN + flow conv + scale
    final_kernel<<<(NPIX + 127) / 128, 128>>>(A, bng, bnb, bnm, bnv, flw, out);
}

// round 2
// speedup vs baseline: 1.7180x; 1.7180x over previous
#include <cuda_runtime.h>
#include <cuda_bf16.h>
#include <math.h>

// ---------------- problem constants ----------------
#define Bn 8
#define Hn 192
#define Wn 192
#define Cn 64
#define NPIX (Bn*Hn*Wn)          // 294912
#define CV 81
#define CIN0 209
#define P0 212                    // padded stride for 209-channel tensors
#define FLOW_SCALE 271.52900393598527f   // sqrt(192^2 + 192^2)
#define BN_EPS 1e-3f

// cost tile geometry
#define TX 32
#define TY 8
#define HALO 4
#define SW (TX + 2*HALO)   // 40
#define SH (TY + 2*HALO)   // 16

// ---------------- scratch (no cudaMalloc allowed) ----------------
__device__ float g_bufA[(size_t)NPIX * P0];   // ~250 MB
__device__ float g_bufB[(size_t)NPIX * P0];   // ~250 MB
__device__ float g_dw0pad[9 * P0];            // padded dw0 weights

// ---------------- helpers ----------------
__device__ __forceinline__ float mish(float x) {
    float sp = fmaxf(x, 0.f) + log1pf(expf(-fabsf(x)));
    return x * tanhf(sp);
}

// ---------------- kernel 0: pad dw0 weights 209 -> 212 ----------------
__global__ void pad_dw0_kernel(const float* __restrict__ dw0)
{
    int idx = blockIdx.x * blockDim.x + threadIdx.x;
    if (idx >= 9 * P0) return;
    int c = idx % P0;
    int k = idx / P0;
    g_dw0pad[idx] = (c < CIN0) ? dw0[k * CIN0 + c] : 0.f;
}

// ---------------- kernel 1: cost volume + concat (smem tiled) ----------------
// out: [NPIX, 212]; channels 0..80 cost, 81..144 prv, 145..208 nxt, 209..211 zero
__global__ __launch_bounds__(256, 1)
void cost_concat_kernel(const float* __restrict__ prv,
                        const float* __restrict__ nxt,
                        float* __restrict__ x0)
{
    __shared__ float s[SH * SW * 4];   // one 4-channel chunk, [y][x][cc]

    const int tid = threadIdx.x;
    const int tx  = tid & 31;
    const int ty  = tid >> 5;
    const int bx  = blockIdx.x;        // 0..5
    const int by  = blockIdx.y;        // 0..23
    const int b   = blockIdx.z;        // 0..7

    const int x = bx * TX + tx;
    const int y = by * TY + ty;
    const int pix = (b * Hn + y) * Wn + x;

    // prv pixel vector in registers (16 float4 = 64 ch)
    const float4* p4 = (const float4*)(prv + (size_t)pix * Cn);
    float4 p[16];
#pragma unroll
    for (int t = 0; t < 16; t++) p[t] = p4[t];

    // cooperative-load index (640 float4 per chunk, 256 threads -> <=3 each)
    int  lsy[3], lsx[3];
    bool lval[3];
    const float* nbase = nxt + (size_t)b * Hn * Wn * Cn;
#pragma unroll
    for (int k = 0; k < 3; k++) {
        int i = tid + k * 256;
        int sy = i / SW, sx = i - sy * SW;
        int gy = by * TY + sy - HALO;
        int gx = bx * TX + sx - HALO;
        lsy[k] = sy; lsx[k] = sx;
        lval[k] = (i < SH * SW) && (gy >= 0) && (gy < Hn) && (gx >= 0) && (gx < Wn);
        // store the gmem offset in lsx when valid to avoid recompute? keep simple:
        lsy[k] = sy * SW + sx;                       // smem pixel index
        lsx[k] = ((gy * Wn) + gx);                   // gmem pixel index (may be junk if !lval)
    }

    float acc[81];
#pragma unroll
    for (int o = 0; o < 81; o++) acc[o] = 0.f;

    float4 ld[3];
    // prefetch chunk 0
#pragma unroll
    for (int k = 0; k < 3; k++) {
        ld[k] = make_float4(0.f, 0.f, 0.f, 0.f);
        if (lval[k]) ld[k] = *(const float4*)(nbase + (size_t)lsx[k] * Cn + 0);
    }

#pragma unroll 1
    for (int ch = 0; ch < 16; ch++) {
        // commit prefetched chunk to smem
#pragma unroll
        for (int k = 0; k < 3; k++) {
            int i = tid + k * 256;
            if (i < SH * SW) *(float4*)&s[lsy[k] * 4] = ld[k];
        }
        __syncthreads();
        // prefetch next chunk (gmem latency overlaps compute)
        if (ch < 15) {
#pragma unroll
            for (int k = 0; k < 3; k++) {
                ld[k] = make_float4(0.f, 0.f, 0.f, 0.f);
                if (lval[k]) ld[k] = *(const float4*)(nbase + (size_t)lsx[k] * Cn + (ch + 1) * 4);
            }
        }
        const float4 pq = p[ch];
#pragma unroll
        for (int dy = 0; dy < 9; dy++) {
#pragma unroll
            for (int dx = 0; dx < 9; dx++) {
                float4 q = *(const float4*)&s[((ty + dy) * SW + (tx + dx)) * 4];
                float a = acc[dy * 9 + dx];
                a = fmaf(pq.x, q.x, a);
                a = fmaf(pq.y, q.y, a);
                a = fmaf(pq.z, q.z, a);
                a = fmaf(pq.w, q.w, a);
                acc[dy * 9 + dx] = a;
            }
        }
        __syncthreads();
    }

    float* out = x0 + (size_t)pix * P0;
#pragma unroll
    for (int o = 0; o < 81; o++) {
        float c = acc[o] * (1.f / 64.f);
        out[o] = (c > 0.f) ? c : 0.1f * c;
    }
#pragma unroll
    for (int t = 0; t < 16; t++) {
        out[CV + 4 * t + 0] = p[t].x;
        out[CV + 4 * t + 1] = p[t].y;
        out[CV + 4 * t + 2] = p[t].z;
        out[CV + 4 * t + 3] = p[t].w;
    }
    const float4* n4 = (const float4*)(nxt + (size_t)pix * Cn);
#pragma unroll
    for (int t = 0; t < 16; t++) {
        float4 q = n4[t];
        out[CV + Cn + 4 * t + 0] = q.x;
        out[CV + Cn + 4 * t + 1] = q.y;
        out[CV + Cn + 4 * t + 2] = q.z;
        out[CV + Cn + 4 * t + 3] = q.w;
    }
    out[209] = 0.f; out[210] = 0.f; out[211] = 0.f;
}

// ---------------- kernel 2: depthwise 3x3 SAME, float4 channels ----------------
// X,Y: [NPIX, stride] ; Wd: [9, stride4*4] (padded); thread = (pix, quad)
__global__ void dw4_kernel(const float* __restrict__ X, const float* __restrict__ Wd,
                           float* __restrict__ Y, int quads, int stride)
{
    int idx = blockIdx.x * blockDim.x + threadIdx.x;
    int total = NPIX * quads;
    if (idx >= total) return;
    int q = idx % quads;
    int pix = idx / quads;
    int w = pix % Wn;
    int h = (pix / Wn) % Hn;
    int b = pix / (Wn * Hn);

    float4 acc = make_float4(0.f, 0.f, 0.f, 0.f);
#pragma unroll
    for (int ky = 0; ky < 3; ky++) {
        int hh = h + ky - 1;
        if (hh < 0 || hh >= Hn) continue;
#pragma unroll
        for (int kx = 0; kx < 3; kx++) {
            int ww = w + kx - 1;
            if (ww < 0 || ww >= Wn) continue;
            float4 xv = *(const float4*)(X + ((size_t)((b * Hn + hh) * Wn + ww)) * stride + q * 4);
            float4 wv = *(const float4*)(Wd + (ky * 3 + kx) * stride + q * 4);
            acc.x = fmaf(xv.x, wv.x, acc.x);
            acc.y = fmaf(xv.y, wv.y, acc.y);
            acc.z = fmaf(xv.z, wv.z, acc.z);
            acc.w = fmaf(xv.w, wv.w, acc.w);
        }
    }
    *(float4*)(Y + (size_t)pix * stride + q * 4) = acc;
}

// ---------------- kernel 3: pointwise GEMM + bias + mish ----------------
template<int BNv, int TN>
__global__ void pw_mish_kernel(const float* __restrict__ X, const float* __restrict__ Wp,
                               const float* __restrict__ bias, float* __restrict__ Y,
                               int K, int strideK)
{
    __shared__ float As[16][64];
    __shared__ float Ws[16][BNv];

    int tid = threadIdx.x;
    int tx = tid % 16;
    int ty = tid / 16;
    int block_px = blockIdx.x * 64;

    float acc[4][TN];
#pragma unroll
    for (int m = 0; m < 4; m++)
#pragma unroll
        for (int j = 0; j < TN; j++) acc[m][j] = 0.f;

    int a_px = tid >> 2;
    int a_k  = (tid & 3) * 4;
    const float* Arow = X + (size_t)(block_px + a_px) * strideK;

    for (int k0 = 0; k0 < K; k0 += 16) {
#pragma unroll
        for (int r = 0; r < 4; r++) {
            int k = k0 + a_k + r;
            As[a_k + r][a_px] = (k < K) ? Arow[k] : 0.f;
        }
#pragma unroll
        for (int i = tid; i < 16 * BNv; i += 256) {
            int kk = i / BNv, n = i % BNv;
            int k = k0 + kk;
            Ws[kk][n] = (k < K) ? Wp[k * BNv + n] : 0.f;
        }
        __syncthreads();
#pragma unroll
        for (int kk = 0; kk < 16; kk++) {
            float a0 = As[kk][ty * 4 + 0];
            float a1 = As[kk][ty * 4 + 1];
            float a2 = As[kk][ty * 4 + 2];
            float a3 = As[kk][ty * 4 + 3];
#pragma unroll
            for (int j = 0; j < TN; j++) {
                float bb = Ws[kk][tx * TN + j];
                acc[0][j] += a0 * bb;
                acc[1][j] += a1 * bb;
                acc[2][j] += a2 * bb;
                acc[3][j] += a3 * bb;
            }
        }
        __syncthreads();
    }

#pragma unroll
    for (int m = 0; m < 4; m++) {
        int px = block_px + ty * 4 + m;
        float* yrow = Y + (size_t)px * BNv;
#pragma unroll
        for (int j = 0; j < TN; j++) {
            int n = tx * TN + j;
            float v = acc[m][j] + bias[n];
            yrow[n] = mish(v);
        }
    }
}

// ---------------- kernel 4: BN + 3x3 flow conv + scale ----------------
__global__ void final_kernel(const float* __restrict__ X,
                             const float* __restrict__ gamma, const float* __restrict__ beta,
                             const float* __restrict__ mean,  const float* __restrict__ var,
                             const float* __restrict__ Wf, float* __restrict__ out)
{
    int pix = blockIdx.x * blockDim.x + threadIdx.x;
    if (pix >= NPIX) return;
    int w = pix % Wn;
    int h = (pix / Wn) % Hn;
    int b = pix / (Wn * Hn);

    float sc[16], sh[16];
#pragma unroll
    for (int c = 0; c < 16; c++) {
        float s = gamma[c] * rsqrtf(var[c] + BN_EPS);
        sc[c] = s;
        sh[c] = beta[c] - mean[c] * s;
    }

    float f0 = 0.f, f1 = 0.f;
#pragma unroll
    for (int ky = 0; ky < 3; ky++) {
        int hh = h + ky - 1;
        if (hh < 0 || hh >= Hn) continue;
#pragma unroll
        for (int kx = 0; kx < 3; kx++) {
            int ww = w + kx - 1;
            if (ww < 0 || ww >= Wn) continue;
            const float* xr = X + ((size_t)((b * Hn + hh) * Wn + ww)) * 16;
            const float* wr = Wf + (ky * 3 + kx) * 16 * 2;
#pragma unroll
            for (int c = 0; c < 16; c++) {
                float xv = xr[c] * sc[c] + sh[c];
                f0 += xv * wr[c * 2 + 0];
                f1 += xv * wr[c * 2 + 1];
            }
        }
    }
    out[(size_t)pix * 2 + 0] = FLOW_SCALE * f0;
    out[(size_t)pix * 2 + 1] = FLOW_SCALE * f1;
}

// ---------------- launch ----------------
extern "C" void kernel_launch(void* const* d_in, const int* in_sizes, int n_in,
                              void* d_out, int out_size)
{
    const float* prv   = (const float*)d_in[0];
    const float* nxt   = (const float*)d_in[1];
    const float* dw0   = (const float*)d_in[2];
    const float* pw0   = (const float*)d_in[3];
    const float* b0    = (const float*)d_in[4];
    const float* dw1   = (const float*)d_in[5];
    const float* pw1   = (const float*)d_in[6];
    const float* b1    = (const float*)d_in[7];
    const float* dw2   = (const float*)d_in[8];
    const float* pw2   = (const float*)d_in[9];
    const float* b2    = (const float*)d_in[10];
    const float* dw3   = (const float*)d_in[11];
    const float* pw3   = (const float*)d_in[12];
    const float* b3    = (const float*)d_in[13];
    const float* bng   = (const float*)d_in[14];
    const float* bnb   = (const float*)d_in[15];
    const float* bnm   = (const float*)d_in[16];
    const float* bnv   = (const float*)d_in[17];
    const float* flw   = (const float*)d_in[18];
    float* out = (float*)d_out;

    float *A = nullptr, *Bb = nullptr, *W0 = nullptr;
    cudaGetSymbolAddress((void**)&A,  g_bufA);
    cudaGetSymbolAddress((void**)&Bb, g_bufB);
    cudaGetSymbolAddress((void**)&W0, g_dw0pad);

    // pad dw0 weights
    pad_dw0_kernel<<<(9 * P0 + 255) / 256, 256>>>(dw0);

    // 1) cost volume + concat -> A [NPIX, 212]
    {
        dim3 grid(Wn / TX, Hn / TY, Bn);
        cost_concat_kernel<<<grid, 256>>>(prv, nxt, A);
    }

    // layer 0: dw(A,212q)->B, pw(B)->A(128)
    {
        int total = NPIX * (P0 / 4);
        dw4_kernel<<<(total + 255) / 256, 256>>>(A, W0, Bb, P0 / 4, P0);
        pw_mish_kernel<128, 8><<<NPIX / 64, 256>>>(Bb, pw0, b0, A, CIN0, P0);
    }
    // layer 1
    {
        int total = NPIX * (128 / 4);
        dw4_kernel<<<(total + 255) / 256, 256>>>(A, dw1, Bb, 128 / 4, 128);
        pw_mish_kernel<64, 4><<<NPIX / 64, 256>>>(Bb, pw1, b1, A, 128, 128);
    }
    // layer 2
    {
        int total = NPIX * (64 / 4);
        dw4_kernel<<<(total + 255) / 256, 256>>>(A, dw2, Bb, 64 / 4, 64);
        pw_mish_kernel<32, 2><<<NPIX / 64, 256>>>(Bb, pw2, b2, A, 64, 64);
    }
    // layer 3
    {
        int total = NPIX * (32 / 4);
        dw4_kernel<<<(total + 255) / 256, 256>>>(A, dw3, Bb, 32 / 4, 32);
        pw_mish_kernel<16, 1><<<NPIX / 64, 256>>>(Bb, pw3, b3, A, 32, 32);
    }
    final_kernel<<<(NPIX + 127) / 128, 128>>>(A, bng, bnb, bnm, bnv, flw, out);
}

// round 3
// speedup vs baseline: 2.2752x; 1.3243x over previous
#include <cuda_runtime.h>
#include <cuda_bf16.h>
#include <math.h>

// ---------------- problem constants ----------------
#define Bn 8
#define Hn 192
#define Wn 192
#define Cn 64
#define NPIX (Bn*Hn*Wn)          // 294912
#define CV 81
#define CIN0 209
#define P0 216                    // padded stride for 209-channel tensors (27 * 8)
#define FLOW_SCALE 271.52900393598527f   // sqrt(192^2 + 192^2)
#define BN_EPS 1e-3f

// cost tile geometry
#define TX 32
#define TY 8
#define HALO 4
#define SW (TX + 2*HALO)   // 40
#define SH (TY + 2*HALO)   // 16

// ---------------- scratch (no cudaMalloc allowed) ----------------
__device__ float g_bufA[(size_t)NPIX * P0];   // ~255 MB
__device__ float g_bufB[(size_t)NPIX * P0];   // ~255 MB
__device__ float g_dw0pad[9 * P0];            // padded dw0 weights
__device__ float g_pw0pad[P0 * 128];          // padded pw0 weights [216][128]

// ---------------- helpers ----------------
__device__ __forceinline__ float mish(float x) {
    float sp = fmaxf(x, 0.f) + log1pf(expf(-fabsf(x)));
    return x * tanhf(sp);
}

// ---------------- kernel 0: pad dw0 + pw0 weights ----------------
__global__ void pad_w_kernel(const float* __restrict__ dw0, const float* __restrict__ pw0)
{
    int idx = blockIdx.x * blockDim.x + threadIdx.x;
    if (idx < 9 * P0) {
        int c = idx % P0;
        int k = idx / P0;
        g_dw0pad[idx] = (c < CIN0) ? dw0[k * CIN0 + c] : 0.f;
    }
    if (idx < P0 * 128) {
        int n = idx % 128;
        int k = idx / 128;
        g_pw0pad[idx] = (k < CIN0) ? pw0[k * 128 + n] : 0.f;
    }
}

// ---------------- kernel 1: cost volume + concat (smem tiled) ----------------
__global__ __launch_bounds__(256, 1)
void cost_concat_kernel(const float* __restrict__ prv,
                        const float* __restrict__ nxt,
                        float* __restrict__ x0)
{
    __shared__ float s[SH * SW * 4];   // one 4-channel chunk, [y][x][cc]

    const int tid = threadIdx.x;
    const int tx  = tid & 31;
    const int ty  = tid >> 5;
    const int bx  = blockIdx.x;
    const int by  = blockIdx.y;
    const int b   = blockIdx.z;

    const int x = bx * TX + tx;
    const int y = by * TY + ty;
    const int pix = (b * Hn + y) * Wn + x;

    const float4* p4 = (const float4*)(prv + (size_t)pix * Cn);
    float4 p[16];
#pragma unroll
    for (int t = 0; t < 16; t++) p[t] = p4[t];

    int  lsm[3], lgm[3];
    bool lval[3];
    const float* nbase = nxt + (size_t)b * Hn * Wn * Cn;
#pragma unroll
    for (int k = 0; k < 3; k++) {
        int i = tid + k * 256;
        int sy = i / SW, sx = i - sy * SW;
        int gy = by * TY + sy - HALO;
        int gx = bx * TX + sx - HALO;
        lval[k] = (i < SH * SW) && (gy >= 0) && (gy < Hn) && (gx >= 0) && (gx < Wn);
        lsm[k] = sy * SW + sx;
        lgm[k] = gy * Wn + gx;
    }

    float acc[81];
#pragma unroll
    for (int o = 0; o < 81; o++) acc[o] = 0.f;

    float4 ld[3];
#pragma unroll
    for (int k = 0; k < 3; k++) {
        ld[k] = make_float4(0.f, 0.f, 0.f, 0.f);
        if (lval[k]) ld[k] = *(const float4*)(nbase + (size_t)lgm[k] * Cn + 0);
    }

#pragma unroll 1
    for (int ch = 0; ch < 16; ch++) {
#pragma unroll
        for (int k = 0; k < 3; k++) {
            int i = tid + k * 256;
            if (i < SH * SW) *(float4*)&s[lsm[k] * 4] = ld[k];
        }
        __syncthreads();
        if (ch < 15) {
#pragma unroll
            for (int k = 0; k < 3; k++) {
                ld[k] = make_float4(0.f, 0.f, 0.f, 0.f);
                if (lval[k]) ld[k] = *(const float4*)(nbase + (size_t)lgm[k] * Cn + (ch + 1) * 4);
            }
        }
        const float4 pq = p[ch];
#pragma unroll
        for (int dy = 0; dy < 9; dy++) {
#pragma unroll
            for (int dx = 0; dx < 9; dx++) {
                float4 q = *(const float4*)&s[((ty + dy) * SW + (tx + dx)) * 4];
                float a = acc[dy * 9 + dx];
                a = fmaf(pq.x, q.x, a);
                a = fmaf(pq.y, q.y, a);
                a = fmaf(pq.z, q.z, a);
                a = fmaf(pq.w, q.w, a);
                acc[dy * 9 + dx] = a;
            }
        }
        __syncthreads();
    }

    float* out = x0 + (size_t)pix * P0;
#pragma unroll
    for (int o = 0; o < 81; o++) {
        float c = acc[o] * (1.f / 64.f);
        out[o] = (c > 0.f) ? c : 0.1f * c;
    }
#pragma unroll
    for (int t = 0; t < 16; t++) {
        out[CV + 4 * t + 0] = p[t].x;
        out[CV + 4 * t + 1] = p[t].y;
        out[CV + 4 * t + 2] = p[t].z;
        out[CV + 4 * t + 3] = p[t].w;
    }
    const float4* n4 = (const float4*)(nxt + (size_t)pix * Cn);
#pragma unroll
    for (int t = 0; t < 16; t++) {
        float4 q = n4[t];
        out[CV + Cn + 4 * t + 0] = q.x;
        out[CV + Cn + 4 * t + 1] = q.y;
        out[CV + Cn + 4 * t + 2] = q.z;
        out[CV + Cn + 4 * t + 3] = q.w;
    }
#pragma unroll
    for (int z = 209; z < P0; z++) out[z] = 0.f;
}

// ---------------- kernel 2: depthwise 3x3 SAME, float4 channels ----------------
__global__ void dw4_kernel(const float* __restrict__ X, const float* __restrict__ Wd,
                           float* __restrict__ Y, int quads, int stride)
{
    int idx = blockIdx.x * blockDim.x + threadIdx.x;
    int total = NPIX * quads;
    if (idx >= total) return;
    int q = idx % quads;
    int pix = idx / quads;
    int w = pix % Wn;
    int h = (pix / Wn) % Hn;
    int b = pix / (Wn * Hn);

    float4 acc = make_float4(0.f, 0.f, 0.f, 0.f);
#pragma unroll
    for (int ky = 0; ky < 3; ky++) {
        int hh = h + ky - 1;
        if (hh < 0 || hh >= Hn) continue;
#pragma unroll
        for (int kx = 0; kx < 3; kx++) {
            int ww = w + kx - 1;
            if (ww < 0 || ww >= Wn) continue;
            float4 xv = *(const float4*)(X + ((size_t)((b * Hn + hh) * Wn + ww)) * stride + q * 4);
            float4 wv = *(const float4*)(Wd + (ky * 3 + kx) * stride + q * 4);
            acc.x = fmaf(xv.x, wv.x, acc.x);
            acc.y = fmaf(xv.y, wv.y, acc.y);
            acc.z = fmaf(xv.z, wv.z, acc.z);
            acc.w = fmaf(xv.w, wv.w, acc.w);
        }
    }
    *(float4*)(Y + (size_t)pix * stride + q * 4) = acc;
}

// ---------------- kernel 3a: big SGEMM + bias + mish (layers 0,1) ----------------
// X:[NPIX, ldX], Wp:[KTILES*8, BN_], Y:[NPIX, BN_]; BM=128, BK=8, 256 threads.
// TN_ in {8,4}; microtile 8 x TN_ per thread.
template<int BN_, int TN_, int KTILES>
__global__ __launch_bounds__(256)
void sgemm_mish(const float* __restrict__ X, int ldX,
                const float* __restrict__ Wp,
                const float* __restrict__ bias,
                float* __restrict__ Y)
{
    __shared__ float As[2][8][128];
    __shared__ float Bs[2][8][BN_];

    const int tid = threadIdx.x;
    const int px0 = blockIdx.x * 128;

    // A loader: 128 rows x 8 k; thread -> (row = tid/2, kquad = (tid&1)*4)
    const int arow = tid >> 1;
    const int acol = (tid & 1) * 4;
    const float* aptr = X + (size_t)(px0 + arow) * ldX + acol;

    // B loader: 8 rows x BN_ cols; BN_*2 loader threads
    constexpr int BLOADERS = BN_ * 2;
    const int brow = tid / (BN_ / 4);
    const int bcol = (tid % (BN_ / 4)) * 4;
    const float* bptr = Wp + (size_t)brow * BN_ + bcol;

    // compute mapping
    const int tcx = tid & 15;        // n group
    const int tcy = tid >> 4;        // m group (0..15)

    float acc[8][TN_];
#pragma unroll
    for (int m = 0; m < 8; m++)
#pragma unroll
        for (int n = 0; n < TN_; n++) acc[m][n] = 0.f;

    float4 av = *(const float4*)aptr;
    float4 bv;
    if (tid < BLOADERS) bv = *(const float4*)bptr;

    // commit tile 0
    As[0][acol + 0][arow] = av.x;
    As[0][acol + 1][arow] = av.y;
    As[0][acol + 2][arow] = av.z;
    As[0][acol + 3][arow] = av.w;
    if (tid < BLOADERS) *(float4*)&Bs[0][brow][bcol] = bv;
    __syncthreads();

#pragma unroll 1
    for (int kt = 0; kt < KTILES; kt++) {
        const int buf = kt & 1;
        if (kt + 1 < KTILES) {
            av = *(const float4*)(aptr + (kt + 1) * 8);
            if (tid < BLOADERS) bv = *(const float4*)(bptr + (size_t)(kt + 1) * 8 * BN_);
        }
#pragma unroll
        for (int kk = 0; kk < 8; kk++) {
            float4 a0 = *(const float4*)&As[buf][kk][tcy * 4];
            float4 a1 = *(const float4*)&As[buf][kk][tcy * 4 + 64];
            float ar[8] = {a0.x, a0.y, a0.z, a0.w, a1.x, a1.y, a1.z, a1.w};
            float br[TN_];
            {
                float4 b0 = *(const float4*)&Bs[buf][kk][tcx * 4];
                br[0] = b0.x; br[1] = b0.y; br[2] = b0.z; br[3] = b0.w;
                if (TN_ == 8) {
                    float4 b1 = *(const float4*)&Bs[buf][kk][tcx * 4 + 64];
                    br[4] = b1.x; br[5] = b1.y; br[6] = b1.z; br[7] = b1.w;
                }
            }
#pragma unroll
            for (int m = 0; m < 8; m++)
#pragma unroll
                for (int n = 0; n < TN_; n++)
                    acc[m][n] = fmaf(ar[m], br[n], acc[m][n]);
        }
        if (kt + 1 < KTILES) {
            const int nb = buf ^ 1;
            As[nb][acol + 0][arow] = av.x;
            As[nb][acol + 1][arow] = av.y;
            As[nb][acol + 2][arow] = av.z;
            As[nb][acol + 3][arow] = av.w;
            if (tid < BLOADERS) *(float4*)&Bs[nb][brow][bcol] = bv;
        }
        __syncthreads();
    }

    // epilogue: bias + mish, float4 stores
    float bb[TN_];
    {
        float4 t0 = *(const float4*)&bias[tcx * 4];
        bb[0] = t0.x; bb[1] = t0.y; bb[2] = t0.z; bb[3] = t0.w;
        if (TN_ == 8) {
            float4 t1 = *(const float4*)&bias[tcx * 4 + 64];
            bb[4] = t1.x; bb[5] = t1.y; bb[6] = t1.z; bb[7] = t1.w;
        }
    }
#pragma unroll
    for (int g = 0; g < 2; g++) {
#pragma unroll
        for (int m = 0; m < 4; m++) {
            int px = px0 + tcy * 4 + m + g * 64;
            float* yr = Y + (size_t)px * BN_;
#pragma unroll
            for (int ng = 0; ng < TN_ / 4; ng++) {
                float4 o;
                o.x = mish(acc[g * 4 + m][ng * 4 + 0] + bb[ng * 4 + 0]);
                o.y = mish(acc[g * 4 + m][ng * 4 + 1] + bb[ng * 4 + 1]);
                o.z = mish(acc[g * 4 + m][ng * 4 + 2] + bb[ng * 4 + 2]);
                o.w = mish(acc[g * 4 + m][ng * 4 + 3] + bb[ng * 4 + 3]);
                *(float4*)&yr[tcx * 4 + ng * 64] = o;
            }
        }
    }
}

// ---------------- kernel 3b: small pointwise GEMM + bias + mish (layers 2,3) ----------------
template<int BNv, int TN>
__global__ void pw_mish_kernel(const float* __restrict__ X, const float* __restrict__ Wp,
                               const float* __restrict__ bias, float* __restrict__ Y,
                               int K, int strideK)
{
    __shared__ float As[16][64];
    __shared__ float Ws[16][BNv];

    int tid = threadIdx.x;
    int tx = tid % 16;
    int ty = tid / 16;
    int block_px = blockIdx.x * 64;

    float acc[4][TN];
#pragma unroll
    for (int m = 0; m < 4; m++)
#pragma unroll
        for (int j = 0; j < TN; j++) acc[m][j] = 0.f;

    int a_px = tid >> 2;
    int a_k  = (tid & 3) * 4;
    const float* Arow = X + (size_t)(block_px + a_px) * strideK;

    for (int k0 = 0; k0 < K; k0 += 16) {
#pragma unroll
        for (int r = 0; r < 4; r++) {
            int k = k0 + a_k + r;
            As[a_k + r][a_px] = (k < K) ? Arow[k] : 0.f;
        }
#pragma unroll
        for (int i = tid; i < 16 * BNv; i += 256) {
            int kk = i / BNv, n = i % BNv;
            int k = k0 + kk;
            Ws[kk][n] = (k < K) ? Wp[k * BNv + n] : 0.f;
        }
        __syncthreads();
#pragma unroll
        for (int kk = 0; kk < 16; kk++) {
            float a0 = As[kk][ty * 4 + 0];
            float a1 = As[kk][ty * 4 + 1];
            float a2 = As[kk][ty * 4 + 2];
            float a3 = As[kk][ty * 4 + 3];
#pragma unroll
            for (int j = 0; j < TN; j++) {
                float bb = Ws[kk][tx * TN + j];
                acc[0][j] += a0 * bb;
                acc[1][j] += a1 * bb;
                acc[2][j] += a2 * bb;
                acc[3][j] += a3 * bb;
            }
        }
        __syncthreads();
    }

#pragma unroll
    for (int m = 0; m < 4; m++) {
        int px = block_px + ty * 4 + m;
        float* yrow = Y + (size_t)px * BNv;
#pragma unroll
        for (int j = 0; j < TN; j++) {
            int n = tx * TN + j;
            float v = acc[m][j] + bias[n];
            yrow[n] = mish(v);
        }
    }
}

// ---------------- kernel 4: BN + 3x3 flow conv + scale ----------------
__global__ void final_kernel(const float* __restrict__ X,
                             const float* __restrict__ gamma, const float* __restrict__ beta,
                             const float* __restrict__ mean,  const float* __restrict__ var,
                             const float* __restrict__ Wf, float* __restrict__ out)
{
    int pix = blockIdx.x * blockDim.x + threadIdx.x;
    if (pix >= NPIX) return;
    int w = pix % Wn;
    int h = (pix / Wn) % Hn;
    int b = pix / (Wn * Hn);

    float sc[16], sh[16];
#pragma unroll
    for (int c = 0; c < 16; c++) {
        float s = gamma[c] * rsqrtf(var[c] + BN_EPS);
        sc[c] = s;
        sh[c] = beta[c] - mean[c] * s;
    }

    float f0 = 0.f, f1 = 0.f;
#pragma unroll
    for (int ky = 0; ky < 3; ky++) {
        int hh = h + ky - 1;
        if (hh < 0 || hh >= Hn) continue;
#pragma unroll
        for (int kx = 0; kx < 3; kx++) {
            int ww = w + kx - 1;
            if (ww < 0 || ww >= Wn) continue;
            const float* xr = X + ((size_t)((b * Hn + hh) * Wn + ww)) * 16;
            const float* wr = Wf + (ky * 3 + kx) * 16 * 2;
#pragma unroll
            for (int c = 0; c < 16; c++) {
                float xv = xr[c] * sc[c] + sh[c];
                f0 += xv * wr[c * 2 + 0];
                f1 += xv * wr[c * 2 + 1];
            }
        }
    }
    out[(size_t)pix * 2 + 0] = FLOW_SCALE * f0;
    out[(size_t)pix * 2 + 1] = FLOW_SCALE * f1;
}

// ---------------- launch ----------------
extern "C" void kernel_launch(void* const* d_in, const int* in_sizes, int n_in,
                              void* d_out, int out_size)
{
    const float* prv   = (const float*)d_in[0];
    const float* nxt   = (const float*)d_in[1];
    const float* dw0   = (const float*)d_in[2];
    const float* pw0   = (const float*)d_in[3];
    const float* b0    = (const float*)d_in[4];
    const float* dw1   = (const float*)d_in[5];
    const float* pw1   = (const float*)d_in[6];
    const float* b1    = (const float*)d_in[7];
    const float* dw2   = (const float*)d_in[8];
    const float* pw2   = (const float*)d_in[9];
    const float* b2    = (const float*)d_in[10];
    const float* dw3   = (const float*)d_in[11];
    const float* pw3   = (const float*)d_in[12];
    const float* b3    = (const float*)d_in[13];
    const float* bng   = (const float*)d_in[14];
    const float* bnb   = (const float*)d_in[15];
    const float* bnm   = (const float*)d_in[16];
    const float* bnv   = (const float*)d_in[17];
    const float* flw   = (const float*)d_in[18];
    float* out = (float*)d_out;

    float *A = nullptr, *Bb = nullptr, *W0 = nullptr, *PW0 = nullptr;
    cudaGetSymbolAddress((void**)&A,   g_bufA);
    cudaGetSymbolAddress((void**)&Bb,  g_bufB);
    cudaGetSymbolAddress((void**)&W0,  g_dw0pad);
    cudaGetSymbolAddress((void**)&PW0, g_pw0pad);

    // pad dw0 + pw0 weights
    pad_w_kernel<<<(P0 * 128 + 255) / 256, 256>>>(dw0, pw0);

    // 1) cost volume + concat -> A [NPIX, 216]
    {
        dim3 grid(Wn / TX, Hn / TY, Bn);
        cost_concat_kernel<<<grid, 256>>>(prv, nxt, A);
    }

    // layer 0: dw(A,216)->B, pw(B)->A(128)
    {
        int total = NPIX * (P0 / 4);
        dw4_kernel<<<(total + 255) / 256, 256>>>(A, W0, Bb, P0 / 4, P0);
        sgemm_mish<128, 8, P0 / 8><<<NPIX / 128, 256>>>(Bb, P0, PW0, b0, A);
    }
    // layer 1: dw(A,128)->B, pw(B)->A(64)
    {
        int total = NPIX * (128 / 4);
        dw4_kernel<<<(total + 255) / 256, 256>>>(A, dw1, Bb, 128 / 4, 128);
        sgemm_mish<64, 4, 128 / 8><<<NPIX / 128, 256>>>(Bb, 128, pw1, b1, A);
    }
    // layer 2: dw(A,64)->B, pw(B)->A(32)
    {
        int total = NPIX * (64 / 4);
        dw4_kernel<<<(total + 255) / 256, 256>>>(A, dw2, Bb, 64 / 4, 64);
        pw_mish_kernel<32, 2><<<NPIX / 64, 256>>>(Bb, pw2, b2, A, 64, 64);
    }
    // layer 3: dw(A,32)->B, pw(B)->A(16)
    {
        int total = NPIX * (32 / 4);
        dw4_kernel<<<(total + 255) / 256, 256>>>(A, dw3, Bb, 32 / 4, 32);
        pw_mish_kernel<16, 1><<<NPIX / 64, 256>>>(Bb, pw3, b3, A, 32, 32);
    }
    final_kernel<<<(NPIX + 127) / 128, 128>>>(A, bng, bnb, bnm, bnv, flw, out);
}